// round 1
// baseline (speedup 1.0000x reference)
#include <cuda_runtime.h>
#include <math.h>

// Problem constants (fixed by setup_inputs)
#define NTOK 4096              // N = H*W = 64*64
#define CH   256               // channels C
#define AF   64                // attention features A = C/4
#define BATCH 4
#define M_TOT (BATCH * NTOK)   // 16384 pixel rows total

// Scratch (device globals — allocation-free per harness rules)
__device__ float g_f[(size_t)M_TOT * AF];   // keys    [B*N, A]  4 MB
__device__ float g_g[(size_t)M_TOT * AF];   // queries [B*N, A]  4 MB
__device__ float g_h[(size_t)M_TOT * CH];   // values  [B*N, C] 16 MB
__device__ float g_o[(size_t)M_TOT * CH];   // attn out[B*N, C] 16 MB

// ---------------------------------------------------------------------------
// Kernel 1: fused 1x1-conv projections  f = x@Wf+bf, g = x@Wg+bg, h = x@Wh+bh
// x viewed as [M_TOT, CH]. Grid-stride over the concatenated [M_TOT, 384]
// output. Early-exits when scale == 0 (layer is identity; o is unused).
// ---------------------------------------------------------------------------
__global__ void proj_kernel(const float* __restrict__ x,
                            const float* __restrict__ Wf, const float* __restrict__ bf,
                            const float* __restrict__ Wg, const float* __restrict__ bg,
                            const float* __restrict__ Wh, const float* __restrict__ bh,
                            const float* __restrict__ scale)
{
    if (*scale == 0.0f) return;   // alpha==0 skip: output never consumed

    const int NOUT = AF + AF + CH;   // 384
    const long total = (long)M_TOT * NOUT;
    for (long idx = (long)blockIdx.x * blockDim.x + threadIdx.x;
         idx < total;
         idx += (long)gridDim.x * blockDim.x)
    {
        const int m = (int)(idx / NOUT);
        const int n = (int)(idx % NOUT);
        const float* xr = x + (long)m * CH;

        if (n < AF) {
            float acc = bf[n];
            #pragma unroll 8
            for (int k = 0; k < CH; k++) acc += xr[k] * Wf[k * AF + n];
            g_f[(long)m * AF + n] = acc;
        } else if (n < 2 * AF) {
            const int nn = n - AF;
            float acc = bg[nn];
            #pragma unroll 8
            for (int k = 0; k < CH; k++) acc += xr[k] * Wg[k * AF + nn];
            g_g[(long)m * AF + nn] = acc;
        } else {
            const int nn = n - 2 * AF;
            float acc = bh[nn];
            #pragma unroll 8
            for (int k = 0; k < CH; k++) acc += xr[k] * Wh[k * CH + nn];
            g_h[(long)m * CH + nn] = acc;
        }
    }
}

// ---------------------------------------------------------------------------
// Kernel 2: per-row attention.
//   s[m] = g_row . f[m]   (A=64 dot)      -> smem (4096 floats, 16 KB)
//   softmax over m (3-pass, fp32)
//   o[c] = sum_m p[m] * h[m][c] / sum     (thread c owns column c, CH==256)
// One query row per loop iteration; 256 threads/block; grid-stride over rows.
// ---------------------------------------------------------------------------
__global__ void attn_kernel(const float* __restrict__ scale)
{
    if (*scale == 0.0f) return;   // alpha==0 skip

    __shared__ float s_s[NTOK];   // scores / probs for one query row
    __shared__ float s_g[AF];     // query row
    __shared__ float red[256];    // reduction buffer

    const int tid = threadIdx.x;

    for (int row = blockIdx.x; row < M_TOT; row += gridDim.x) {
        const int b = row / NTOK;
        const float* __restrict__ fb   = g_f + (long)b * NTOK * AF;
        const float* __restrict__ hb   = g_h + (long)b * NTOK * CH;
        const float* __restrict__ grow = g_g + (long)row * AF;

        if (tid < AF) s_g[tid] = grow[tid];
        __syncthreads();

        // Pass 1: scores + local max
        float lmax = -INFINITY;
        for (int m = tid; m < NTOK; m += 256) {
            const float* fr = fb + (long)m * AF;
            float acc = 0.0f;
            #pragma unroll
            for (int d = 0; d < AF; d++) acc += s_g[d] * fr[d];
            s_s[m] = acc;
            lmax = fmaxf(lmax, acc);
        }
        red[tid] = lmax;
        __syncthreads();
        for (int st = 128; st > 0; st >>= 1) {
            if (tid < st) red[tid] = fmaxf(red[tid], red[tid + st]);
            __syncthreads();
        }
        const float mx = red[0];
        __syncthreads();

        // Pass 2: exp + local sum
        float lsum = 0.0f;
        for (int m = tid; m < NTOK; m += 256) {
            const float p = expf(s_s[m] - mx);
            s_s[m] = p;
            lsum += p;
        }
        red[tid] = lsum;
        __syncthreads();
        for (int st = 128; st > 0; st >>= 1) {
            if (tid < st) red[tid] += red[tid + st];
            __syncthreads();
        }
        const float inv = 1.0f / red[0];
        __syncthreads();

        // Pass 3: o[row][c],  c == tid  (coalesced across threads per m)
        float acc = 0.0f;
        for (int m = 0; m < NTOK; m++) acc += s_s[m] * hb[(long)m * CH + tid];
        g_o[(long)row * CH + tid] = acc * inv;

        __syncthreads();   // protect s_g / s_s before next row
    }
}

// ---------------------------------------------------------------------------
// Kernel 3: y = scale * o + x   (float4-vectorized).
// When scale == 0 this is a pure copy and never reads o.
// ---------------------------------------------------------------------------
__global__ void final_kernel(const float* __restrict__ x,
                             const float* __restrict__ scale,
                             float* __restrict__ out, int n4)
{
    const int i = blockIdx.x * blockDim.x + threadIdx.x;
    if (i >= n4) return;
    const float sc = *scale;                  // uniform; no divergence
    float4 v = ((const float4*)x)[i];
    if (sc != 0.0f) {
        const float4 ov = ((const float4*)g_o)[i];
        v.x += sc * ov.x; v.y += sc * ov.y;
        v.z += sc * ov.z; v.w += sc * ov.w;
    }
    ((float4*)out)[i] = v;
}

// ---------------------------------------------------------------------------
// Inputs (metadata order): x, Wf, bf, Wg, bg, Wh, bh, scale
// ---------------------------------------------------------------------------
extern "C" void kernel_launch(void* const* d_in, const int* in_sizes, int n_in,
                              void* d_out, int out_size)
{
    const float* x     = (const float*)d_in[0];
    const float* Wf    = (const float*)d_in[1];
    const float* bf    = (const float*)d_in[2];
    const float* Wg    = (const float*)d_in[3];
    const float* bg    = (const float*)d_in[4];
    const float* Wh    = (const float*)d_in[5];
    const float* bh    = (const float*)d_in[6];
    const float* scale = (const float*)d_in[7];
    float* out = (float*)d_out;

    (void)in_sizes; (void)n_in;

    proj_kernel<<<2048, 256>>>(x, Wf, bf, Wg, bg, Wh, bh, scale);
    attn_kernel<<<1024, 256>>>(scale);

    const int n4 = out_size / 4;              // 1,048,576 float4s
    final_kernel<<<(n4 + 255) / 256, 256>>>(x, scale, out, n4);
}